// round 16
// baseline (speedup 1.0000x reference)
#include <cuda_runtime.h>
#include <cuda_bf16.h>

// Problem constants
#define B_  8
#define C_  256
#define O_  256
#define H_  64
#define W_  64
#define HW_ 4096
#define KK_ 9
#define WROW_ 24

// Static scratch: weights pre-split (bf16 hi/lo) pre-staged in the exact smem
// tile layout [kk][chunk16][split][o][24-padded]. 3.4 MiB.
__device__ __nv_bfloat16 g_ws[KK_ * 16 * 2 * O_ * WROW_];

// dynamic smem layout (bytes)
#define SM_W    0                      // w tiles: 2 bufs x 2 spl x 256 x 24 x 2B = 49152
#define SM_S    49152                  // s tiles: 2 bufs x 2 spl x 64 x 24 x 2B  = 12288
#define SM_PW   61440                  // pwgt: 9*4*64 floats                     =  9216
#define SM_PS   70656                  // pspat: 9*2*64 ints                      =  4608
#define SM_MB   75264                  // mbarrier (8B)
#define SM_TOT  75280
#define W_BUF   12288                  // elems per w buffer
#define W_SPL   6144
#define S_BUF   3072                   // elems per s buffer
#define S_SPL   1536
#define W_TILE_BYTES 24576

__device__ __forceinline__ unsigned smem_u32(const void* p) {
    unsigned r;
    asm("{ .reg .u64 t; cvta.to.shared.u64 t, %1; cvt.u32.u64 %0, t; }"
        : "=r"(r) : "l"(p));
    return r;
}
__device__ __forceinline__ unsigned pkbf(__nv_bfloat16 a, __nv_bfloat16 b) {
    return (unsigned)__bfloat16_as_ushort(a) |
           ((unsigned)__bfloat16_as_ushort(b) << 16);
}
__device__ __forceinline__ void mbar_init(unsigned mbar, unsigned cnt) {
    asm volatile("mbarrier.init.shared.b64 [%0], %1;" :: "r"(mbar), "r"(cnt) : "memory");
}
__device__ __forceinline__ void mbar_expect_tx(unsigned mbar, unsigned bytes) {
    asm volatile("mbarrier.arrive.expect_tx.shared.b64 _, [%0], %1;"
                 :: "r"(mbar), "r"(bytes) : "memory");
}
__device__ __forceinline__ void mbar_wait(unsigned mbar, unsigned parity) {
    asm volatile(
        "{\n\t"
        ".reg .pred P;\n\t"
        "WL_%=:\n\t"
        "mbarrier.try_wait.parity.shared.b64 P, [%0], %1;\n\t"
        "@P bra.uni WD_%=;\n\t"
        "bra.uni WL_%=;\n\t"
        "WD_%=:\n\t"
        "}"
        :: "r"(mbar), "r"(parity) : "memory");
}
__device__ __forceinline__ void bulk_copy(unsigned dst, const void* src,
                                          unsigned bytes, unsigned mbar) {
    asm volatile(
        "cp.async.bulk.shared::cta.global.mbarrier::complete_tx::bytes "
        "[%0], [%1], %2, [%3];"
        :: "r"(dst), "l"(src), "r"(bytes), "r"(mbar) : "memory");
}

// ---------------------------------------------------------------------------
// Kernel 1: weight (O,C,3,3) fp32 -> staged bf16 hi/lo tiles (pad = 0)
// ---------------------------------------------------------------------------
__global__ void dcn_split_w(const float* __restrict__ w) {
    int i = blockIdx.x * 256 + threadIdx.x;
    if (i >= KK_ * 16 * 2 * O_ * WROW_) return;
    int e     = i % WROW_;
    int o     = (i / WROW_) & 255;
    int split = (i / (WROW_ * 256)) & 1;
    int chunk = (i / (WROW_ * 512)) & 15;
    int kk    = i / (WROW_ * 512 * 16);
    __nv_bfloat16 val = __float2bfloat16_rn(0.0f);
    if (e < 16) {
        int c = (chunk << 4) + e;
        float v = w[o * 2304 + c * 9 + kk];
        __nv_bfloat16 hi = __float2bfloat16_rn(v);
        val = split == 0 ? hi
                         : __float2bfloat16_rn(v - __bfloat162float(hi));
    }
    g_ws[i] = val;
}

// ---------------------------------------------------------------------------
// Kernel 2: fused bilinear-im2col + bf16 tensor-core GEMM (3-term split).
// Per stage: ONE cp.async.bulk prefetches w(s+1) via mbarrier; gather LDGs
// for s(s+1) interleaved with the mma halves; packed uint2 s-stores.
// Gather mapping: gc=tid&3 (c sub-group), gp=tid>>2 (position) -> 4-lane
// broadcast on corner loads, 3-wavefront packed stores.
// ---------------------------------------------------------------------------
__global__ __launch_bounds__(256, 2)
void dcn_main(const float* __restrict__ x,      // (B, C, H, W)
              const float* __restrict__ coff,   // (B, 2*KK, H, W)
              const float* __restrict__ cwt,    // (B, KK, H, W)
              const float* __restrict__ bias,   // (O)
              float* __restrict__ out)          // (B, O, H, W)
{
    extern __shared__ char smem_raw[];
    __nv_bfloat16* w_sm = (__nv_bfloat16*)(smem_raw + SM_W);
    __nv_bfloat16* s_sm = (__nv_bfloat16*)(smem_raw + SM_S);
    float*         pwgt = (float*)(smem_raw + SM_PW);
    int*           pspat = (int*)(smem_raw + SM_PS);
    const unsigned mbar = smem_u32(smem_raw + SM_MB);

    const int cta = blockIdx.x;        // 512 CTAs
    const int b   = cta >> 6;
    const int y   = cta & 63;

    const int tid  = threadIdx.x;
    const int wrp  = tid >> 5;
    const int lane = tid & 31;
    const int ow   = wrp & 3;          // o-group: o_base = ow*64
    const int pw   = wrp >> 2;         // p-group: p_base = pw*32

    const float* xbb = x + ((long)b << 20);

    if (tid == 0) mbar_init(mbar, 1);

    // ---- one-time prep: all taps' corner indices + folded weights ----
    for (int i = tid; i < KK_ * 64; i += 256) {
        int kk = i >> 6;
        int pp = i & 63;
        int base_oy = ((b * 18 + 2 * kk) * 64 + y) * 64 + pp;
        float oy = __ldg(&coff[base_oy]);
        float ox = __ldg(&coff[base_oy + HW_]);
        float cw = __ldg(&cwt[((b * 9 + kk) * 64 + y) * 64 + pp]);
        int ky = kk / 3;
        int kx = kk - ky * 3;
        float py = (float)(y  - 1 + ky) + oy;
        float px = (float)(pp - 1 + kx) + ox;
        float fy = floorf(py), fx = floorf(px);
        int   y0 = (int)fy,    x0 = (int)fx;
        float wy1 = py - fy, wy0 = 1.0f - wy1;
        float wx1 = px - fx, wx0 = 1.0f - wx1;
        bool vy0 = (y0 >= 0)  && (y0 < H_);
        bool vy1 = (y0 >= -1) && (y0 < H_ - 1);
        bool vx0 = (x0 >= 0)  && (x0 < W_);
        bool vx1 = (x0 >= -1) && (x0 < W_ - 1);
        int yc0 = max(0, min(H_ - 1, y0));
        int yc1 = max(0, min(H_ - 1, y0 + 1));
        int xc0 = max(0, min(W_ - 1, x0));
        int xc1 = max(0, min(W_ - 1, x0 + 1));
        int s0 = (yc0 << 6) + xc0, s1 = (yc0 << 6) + xc1;
        int s2 = (yc1 << 6) + xc0, s3 = (yc1 << 6) + xc1;
        pspat[(kk << 7) + pp]      = s0 | (s1 << 16);
        pspat[(kk << 7) + 64 + pp] = s2 | (s3 << 16);
        pwgt[(kk << 8) + pp]        = (vy0 && vx0) ? cw * wy0 * wx0 : 0.0f;
        pwgt[(kk << 8) + 64 + pp]   = (vy0 && vx1) ? cw * wy0 * wx1 : 0.0f;
        pwgt[(kk << 8) + 128 + pp]  = (vy1 && vx0) ? cw * wy1 * wx0 : 0.0f;
        pwgt[(kk << 8) + 192 + pp]  = (vy1 && vx1) ? cw * wy1 * wx1 : 0.0f;
    }
    __syncthreads();

    float acc[2][8][4];
#pragma unroll
    for (int i = 0; i < 2; ++i)
#pragma unroll
        for (int j = 0; j < 8; ++j)
#pragma unroll
            for (int k = 0; k < 4; ++k) acc[i][j][k] = 0.0f;

    const int gc = tid & 3;            // gather: c sub-group 0..3 (4 c's each)
    const int gp = tid >> 2;           // gather: position 0..63

    const int a_row_off = (lane & 15);
    const int a_col_off = (lane >> 4) << 3;
    const int b_row_off = ((lane >> 4) << 3) + (lane & 7);
    const int b_col_off = ((lane >> 3) & 1) << 3;

    const unsigned w_sm_base = smem_u32(w_sm);

    unsigned ph = 0;

    // ---- prologue: stage-0 w via bulk copy, stage-0 s gathered directly ----
    if (tid == 0) {
        mbar_expect_tx(mbar, W_TILE_BYTES);
        bulk_copy(w_sm_base, (const char*)g_ws, W_TILE_BYTES, mbar);
    }
    {
        int pk01 = pspat[gp];
        int pk23 = pspat[64 + gp];
        int sp0 = pk01 & 0xFFFF, sp1 = ((unsigned)pk01) >> 16;
        int sp2 = pk23 & 0xFFFF, sp3 = ((unsigned)pk23) >> 16;
        float g0 = pwgt[gp], g1 = pwgt[64 + gp];
        float g2 = pwgt[128 + gp], g3 = pwgt[192 + gp];
        __nv_bfloat16 hv[4], lv[4];
#pragma unroll
        for (int j = 0; j < 4; ++j) {
            const float* pl = xbb + (((gc << 2) + j) << 12);
            float v = g0 * __ldg(pl + sp0) + g1 * __ldg(pl + sp1)
                    + g2 * __ldg(pl + sp2) + g3 * __ldg(pl + sp3);
            hv[j] = __float2bfloat16_rn(v);
            lv[j] = __float2bfloat16_rn(v - __bfloat162float(hv[j]));
        }
        *(uint2*)(s_sm + gp * WROW_ + (gc << 2)) =
            make_uint2(pkbf(hv[0], hv[1]), pkbf(hv[2], hv[3]));
        *(uint2*)(s_sm + S_SPL + gp * WROW_ + (gc << 2)) =
            make_uint2(pkbf(lv[0], lv[1]), pkbf(lv[2], lv[3]));
    }
    mbar_wait(mbar, ph); ph ^= 1;
    __syncthreads();

    // ---- 144 pipelined stages ----
    for (int s = 0; s < 144; ++s) {
        const __nv_bfloat16* sb = s_sm + (s & 1) * S_BUF;
        const __nv_bfloat16* wb = w_sm + (s & 1) * W_BUF;
        const int sn = s + 1;
        const int kk2 = sn >> 4;
        const int c0n = (sn & 15) << 4;

        // prefetch w(s+1): single bulk copy
        if (s < 143 && tid == 0) {
            mbar_expect_tx(mbar, W_TILE_BYTES);
            bulk_copy(w_sm_base + (unsigned)((sn & 1) * W_TILE_BYTES),
                      (const char*)g_ws + (size_t)sn * W_TILE_BYTES,
                      W_TILE_BYTES, mbar);
        }

        // next-stage gather state
        int sp0 = 0, sp1 = 0, sp2 = 0, sp3 = 0;
        float g0 = 0, g1 = 0, g2 = 0, g3 = 0;
        const float* pl_base = xbb;
        if (s < 143) {
            int pk01 = pspat[(kk2 << 7) + gp];
            int pk23 = pspat[(kk2 << 7) + 64 + gp];
            sp0 = pk01 & 0xFFFF; sp1 = ((unsigned)pk01) >> 16;
            sp2 = pk23 & 0xFFFF; sp3 = ((unsigned)pk23) >> 16;
            g0 = pwgt[(kk2 << 8) + gp];
            g1 = pwgt[(kk2 << 8) + 64 + gp];
            g2 = pwgt[(kk2 << 8) + 128 + gp];
            g3 = pwgt[(kk2 << 8) + 192 + gp];
            pl_base = xbb + ((c0n + (gc << 2)) << 12);
        }

        // A fragments (stage s)
        unsigned ah[2][4], al[2][4];
#pragma unroll
        for (int pt = 0; pt < 2; ++pt) {
            int prow = (pw << 5) + (pt << 4) + a_row_off;
            unsigned addr_h = smem_u32(sb + prow * WROW_ + a_col_off);
            unsigned addr_l = smem_u32(sb + S_SPL + prow * WROW_ + a_col_off);
            asm volatile("ldmatrix.sync.aligned.m8n8.x4.shared.b16 {%0,%1,%2,%3}, [%4];"
                : "=r"(ah[pt][0]), "=r"(ah[pt][1]), "=r"(ah[pt][2]), "=r"(ah[pt][3])
                : "r"(addr_h));
            asm volatile("ldmatrix.sync.aligned.m8n8.x4.shared.b16 {%0,%1,%2,%3}, [%4];"
                : "=r"(al[pt][0]), "=r"(al[pt][1]), "=r"(al[pt][2]), "=r"(al[pt][3])
                : "r"(addr_l));
        }

#define MMA(A, B0, B1, D) \
    asm volatile("mma.sync.aligned.m16n8k16.row.col.f32.bf16.bf16.f32 " \
        "{%0,%1,%2,%3},{%4,%5,%6,%7},{%8,%9},{%0,%1,%2,%3};" \
        : "+f"(D[0]), "+f"(D[1]), "+f"(D[2]), "+f"(D[3]) \
        : "r"(A[0]), "r"(A[1]), "r"(A[2]), "r"(A[3]), "r"(B0), "r"(B1))

#define MMA_OTP(otp_) do { \
    int orow = (ow << 6) + ((otp_) << 4) + b_row_off; \
    unsigned addr_h = smem_u32(wb + orow * WROW_ + b_col_off); \
    unsigned addr_l = smem_u32(wb + W_SPL + orow * WROW_ + b_col_off); \
    unsigned bh[4], bl[4]; \
    asm volatile("ldmatrix.sync.aligned.m8n8.x4.shared.b16 {%0,%1,%2,%3}, [%4];" \
        : "=r"(bh[0]), "=r"(bh[1]), "=r"(bh[2]), "=r"(bh[3]) : "r"(addr_h)); \
    asm volatile("ldmatrix.sync.aligned.m8n8.x4.shared.b16 {%0,%1,%2,%3}, [%4];" \
        : "=r"(bl[0]), "=r"(bl[1]), "=r"(bl[2]), "=r"(bl[3]) : "r"(addr_l)); \
    _Pragma("unroll") \
    for (int sub = 0; sub < 2; ++sub) { \
        int ot = ((otp_) << 1) + sub; \
        _Pragma("unroll") \
        for (int pt = 0; pt < 2; ++pt) { \
            float* d = acc[pt][ot]; \
            MMA(ah[pt], bh[sub * 2], bh[sub * 2 + 1], d); \
            MMA(al[pt], bh[sub * 2], bh[sub * 2 + 1], d); \
            MMA(ah[pt], bl[sub * 2], bl[sub * 2 + 1], d); \
        } \
    } \
} while (0)

        // ---- half 0: issue 8 gather loads (c j=0,1), mma otp 0-1, pack ----
        float la[8];
        if (s < 143) {
#pragma unroll
            for (int i = 0; i < 2; ++i) {
                const float* pl = pl_base + (i << 12);
                la[i * 4 + 0] = __ldg(pl + sp0);
                la[i * 4 + 1] = __ldg(pl + sp1);
                la[i * 4 + 2] = __ldg(pl + sp2);
                la[i * 4 + 3] = __ldg(pl + sp3);
            }
        }
        MMA_OTP(0);
        MMA_OTP(1);
        unsigned uh_x = 0, ul_x = 0;
        if (s < 143) {
            float v0 = g0 * la[0] + g1 * la[1] + g2 * la[2] + g3 * la[3];
            float v1 = g0 * la[4] + g1 * la[5] + g2 * la[6] + g3 * la[7];
            __nv_bfloat16 h0 = __float2bfloat16_rn(v0);
            __nv_bfloat16 h1 = __float2bfloat16_rn(v1);
            __nv_bfloat16 l0 = __float2bfloat16_rn(v0 - __bfloat162float(h0));
            __nv_bfloat16 l1 = __float2bfloat16_rn(v1 - __bfloat162float(h1));
            uh_x = pkbf(h0, h1);
            ul_x = pkbf(l0, l1);
        }

        // ---- half 1: issue 8 gather loads (c j=2,3), mma otp 2-3, store ----
        float lb[8];
        if (s < 143) {
#pragma unroll
            for (int i = 0; i < 2; ++i) {
                const float* pl = pl_base + ((i + 2) << 12);
                lb[i * 4 + 0] = __ldg(pl + sp0);
                lb[i * 4 + 1] = __ldg(pl + sp1);
                lb[i * 4 + 2] = __ldg(pl + sp2);
                lb[i * 4 + 3] = __ldg(pl + sp3);
            }
        }
        MMA_OTP(2);
        MMA_OTP(3);
        if (s < 143) {
            float v2 = g0 * lb[0] + g1 * lb[1] + g2 * lb[2] + g3 * lb[3];
            float v3 = g0 * lb[4] + g1 * lb[5] + g2 * lb[6] + g3 * lb[7];
            __nv_bfloat16 h2 = __float2bfloat16_rn(v2);
            __nv_bfloat16 h3 = __float2bfloat16_rn(v3);
            __nv_bfloat16 l2 = __float2bfloat16_rn(v2 - __bfloat162float(h2));
            __nv_bfloat16 l3 = __float2bfloat16_rn(v3 - __bfloat162float(h3));
            __nv_bfloat16* sbn = s_sm + (sn & 1) * S_BUF;
            *(uint2*)(sbn + gp * WROW_ + (gc << 2)) =
                make_uint2(uh_x, pkbf(h2, h3));
            *(uint2*)(sbn + S_SPL + gp * WROW_ + (gc << 2)) =
                make_uint2(ul_x, pkbf(l2, l3));
        }
#undef MMA_OTP
#undef MMA

        if (s < 143) { mbar_wait(mbar, ph); ph ^= 1; }
        __syncthreads();
    }

    // ---- epilogue: bias + fp32 stores ----
    const long ob_base = ((long)b << 8);
#pragma unroll
    for (int ot = 0; ot < 8; ++ot) {
        int oc = (ow << 6) + (ot << 3) + ((lane & 3) << 1);
        float b0 = __ldg(&bias[oc]);
        float b1 = __ldg(&bias[oc + 1]);
        float* o0p = out + ((ob_base + oc) << 12) + (y << 6);
        float* o1p = out + ((ob_base + oc + 1) << 12) + (y << 6);
#pragma unroll
        for (int pt = 0; pt < 2; ++pt) {
            const float* d = acc[pt][ot];
            int r0 = (pw << 5) + (pt << 4) + (lane >> 2);
            int r1 = r0 + 8;
            o0p[r0] = d[0] + b0;
            o1p[r0] = d[1] + b1;
            o0p[r1] = d[2] + b0;
            o1p[r1] = d[3] + b1;
        }
    }
}

// ---------------------------------------------------------------------------
// Launch: inputs per metadata order: input, coord_offset, coord_weight, weight, bias
// ---------------------------------------------------------------------------
extern "C" void kernel_launch(void* const* d_in, const int* in_sizes, int n_in,
                              void* d_out, int out_size) {
    const float* x    = (const float*)d_in[0];
    const float* coff = (const float*)d_in[1];
    const float* cwt  = (const float*)d_in[2];
    const float* wt   = (const float*)d_in[3];
    const float* bias = (const float*)d_in[4];
    float* out = (float*)d_out;

    static int smem_set = 0;
    if (!smem_set) {
        cudaFuncSetAttribute(dcn_main,
                             cudaFuncAttributeMaxDynamicSharedMemorySize,
                             SM_TOT);
        smem_set = 1;
    }

    int n_ws = KK_ * 16 * 2 * O_ * WROW_;
    dcn_split_w<<<(n_ws + 255) / 256, 256>>>(wt);
    dcn_main<<<B_ * H_, 256, SM_TOT>>>(x, coff, cwt, bias, out);
}

// round 17
// speedup vs baseline: 1.7716x; 1.7716x over previous
#include <cuda_runtime.h>
#include <cuda_bf16.h>

// Problem constants
#define B_  8
#define C_  256
#define O_  256
#define H_  64
#define W_  64
#define HW_ 4096
#define KK_ 9
#define WROW_ 24

// Static scratch: weights pre-split (bf16 hi/lo) pre-staged in the exact smem
// tile layout [kk][chunk16][split][o][24-padded]. 3.4 MiB.
__device__ __nv_bfloat16 g_ws[KK_ * 16 * 2 * O_ * WROW_];

// dynamic smem layout (bytes)
#define SM_W    0                      // w tiles: 2 bufs x 2 spl x 256 x 24 x 2B = 49152
#define SM_S    49152                  // s tiles: 2 bufs x 2 spl x 64 x 24 x 2B  = 12288
#define SM_PW   61440                  // pwgt: 9*4*64 floats                     =  9216
#define SM_PS   70656                  // pspat: 9*2*64 ints                      =  4608
#define SM_MB   75264                  // mbarrier (8B)
#define SM_TOT  75280
#define W_BUF   12288                  // elems per w buffer
#define W_SPL   6144
#define S_BUF   3072                   // elems per s buffer
#define S_SPL   1536
#define W_TILE_BYTES 24576

__device__ __forceinline__ unsigned smem_u32(const void* p) {
    unsigned r;
    asm("{ .reg .u64 t; cvta.to.shared.u64 t, %1; cvt.u32.u64 %0, t; }"
        : "=r"(r) : "l"(p));
    return r;
}
__device__ __forceinline__ unsigned pkbf(__nv_bfloat16 a, __nv_bfloat16 b) {
    return (unsigned)__bfloat16_as_ushort(a) |
           ((unsigned)__bfloat16_as_ushort(b) << 16);
}
__device__ __forceinline__ void mbar_init(unsigned mbar, unsigned cnt) {
    asm volatile("mbarrier.init.shared.b64 [%0], %1;" :: "r"(mbar), "r"(cnt) : "memory");
}
__device__ __forceinline__ void mbar_expect_tx(unsigned mbar, unsigned bytes) {
    asm volatile("mbarrier.arrive.expect_tx.shared.b64 _, [%0], %1;"
                 :: "r"(mbar), "r"(bytes) : "memory");
}
__device__ __forceinline__ void mbar_wait(unsigned mbar, unsigned parity) {
    asm volatile(
        "{\n\t"
        ".reg .pred P;\n\t"
        "WL_%=:\n\t"
        "mbarrier.try_wait.parity.shared.b64 P, [%0], %1;\n\t"
        "@P bra.uni WD_%=;\n\t"
        "bra.uni WL_%=;\n\t"
        "WD_%=:\n\t"
        "}"
        :: "r"(mbar), "r"(parity) : "memory");
}
__device__ __forceinline__ void bulk_copy(unsigned dst, const void* src,
                                          unsigned bytes, unsigned mbar) {
    asm volatile(
        "cp.async.bulk.shared::cta.global.mbarrier::complete_tx::bytes "
        "[%0], [%1], %2, [%3];"
        :: "r"(dst), "l"(src), "r"(bytes), "r"(mbar) : "memory");
}

// ---------------------------------------------------------------------------
// Kernel 1: weight (O,C,3,3) fp32 -> staged bf16 hi/lo tiles (pad = 0)
// ---------------------------------------------------------------------------
__global__ void dcn_split_w(const float* __restrict__ w) {
    int i = blockIdx.x * 256 + threadIdx.x;
    if (i >= KK_ * 16 * 2 * O_ * WROW_) return;
    int e     = i % WROW_;
    int o     = (i / WROW_) & 255;
    int split = (i / (WROW_ * 256)) & 1;
    int chunk = (i / (WROW_ * 512)) & 15;
    int kk    = i / (WROW_ * 512 * 16);
    __nv_bfloat16 val = __float2bfloat16_rn(0.0f);
    if (e < 16) {
        int c = (chunk << 4) + e;
        float v = w[o * 2304 + c * 9 + kk];
        __nv_bfloat16 hi = __float2bfloat16_rn(v);
        val = split == 0 ? hi
                         : __float2bfloat16_rn(v - __bfloat162float(hi));
    }
    g_ws[i] = val;
}

// ---------------------------------------------------------------------------
// Kernel 2: fused bilinear-im2col + bf16 tensor-core GEMM (3-term split).
// Per stage: ONE cp.async.bulk prefetches w(s+1) via mbarrier; gather LDGs
// for s(s+1) interleaved with the mma halves; packed uint2 s-stores.
// Gather mapping (coalescing-audited): gp=tid&63 (position), gc=tid>>6
// (c sub-group) -> each corner LDG has 32 consecutive positions in ONE
// c-plane (~2 lines/warp); stores are packed uint2 (24 wf/warp/stage).
// ---------------------------------------------------------------------------
__global__ __launch_bounds__(256, 2)
void dcn_main(const float* __restrict__ x,      // (B, C, H, W)
              const float* __restrict__ coff,   // (B, 2*KK, H, W)
              const float* __restrict__ cwt,    // (B, KK, H, W)
              const float* __restrict__ bias,   // (O)
              float* __restrict__ out)          // (B, O, H, W)
{
    extern __shared__ char smem_raw[];
    __nv_bfloat16* w_sm = (__nv_bfloat16*)(smem_raw + SM_W);
    __nv_bfloat16* s_sm = (__nv_bfloat16*)(smem_raw + SM_S);
    float*         pwgt = (float*)(smem_raw + SM_PW);
    int*           pspat = (int*)(smem_raw + SM_PS);
    const unsigned mbar = smem_u32(smem_raw + SM_MB);

    const int cta = blockIdx.x;        // 512 CTAs
    const int b   = cta >> 6;
    const int y   = cta & 63;

    const int tid  = threadIdx.x;
    const int wrp  = tid >> 5;
    const int lane = tid & 31;
    const int ow   = wrp & 3;          // o-group: o_base = ow*64
    const int pw   = wrp >> 2;         // p-group: p_base = pw*32

    const float* xbb = x + ((long)b << 20);

    if (tid == 0) mbar_init(mbar, 1);

    // ---- one-time prep: all taps' corner indices + folded weights ----
    for (int i = tid; i < KK_ * 64; i += 256) {
        int kk = i >> 6;
        int pp = i & 63;
        int base_oy = ((b * 18 + 2 * kk) * 64 + y) * 64 + pp;
        float oy = __ldg(&coff[base_oy]);
        float ox = __ldg(&coff[base_oy + HW_]);
        float cw = __ldg(&cwt[((b * 9 + kk) * 64 + y) * 64 + pp]);
        int ky = kk / 3;
        int kx = kk - ky * 3;
        float py = (float)(y  - 1 + ky) + oy;
        float px = (float)(pp - 1 + kx) + ox;
        float fy = floorf(py), fx = floorf(px);
        int   y0 = (int)fy,    x0 = (int)fx;
        float wy1 = py - fy, wy0 = 1.0f - wy1;
        float wx1 = px - fx, wx0 = 1.0f - wx1;
        bool vy0 = (y0 >= 0)  && (y0 < H_);
        bool vy1 = (y0 >= -1) && (y0 < H_ - 1);
        bool vx0 = (x0 >= 0)  && (x0 < W_);
        bool vx1 = (x0 >= -1) && (x0 < W_ - 1);
        int yc0 = max(0, min(H_ - 1, y0));
        int yc1 = max(0, min(H_ - 1, y0 + 1));
        int xc0 = max(0, min(W_ - 1, x0));
        int xc1 = max(0, min(W_ - 1, x0 + 1));
        int s0 = (yc0 << 6) + xc0, s1 = (yc0 << 6) + xc1;
        int s2 = (yc1 << 6) + xc0, s3 = (yc1 << 6) + xc1;
        pspat[(kk << 7) + pp]      = s0 | (s1 << 16);
        pspat[(kk << 7) + 64 + pp] = s2 | (s3 << 16);
        pwgt[(kk << 8) + pp]        = (vy0 && vx0) ? cw * wy0 * wx0 : 0.0f;
        pwgt[(kk << 8) + 64 + pp]   = (vy0 && vx1) ? cw * wy0 * wx1 : 0.0f;
        pwgt[(kk << 8) + 128 + pp]  = (vy1 && vx0) ? cw * wy1 * wx0 : 0.0f;
        pwgt[(kk << 8) + 192 + pp]  = (vy1 && vx1) ? cw * wy1 * wx1 : 0.0f;
    }
    __syncthreads();

    float acc[2][8][4];
#pragma unroll
    for (int i = 0; i < 2; ++i)
#pragma unroll
        for (int j = 0; j < 8; ++j)
#pragma unroll
            for (int k = 0; k < 4; ++k) acc[i][j][k] = 0.0f;

    const int gp = tid & 63;           // gather: position 0..63 (coalesced!)
    const int gc = tid >> 6;           // gather: c sub-group 0..3 (4 c's each)

    const int a_row_off = (lane & 15);
    const int a_col_off = (lane >> 4) << 3;
    const int b_row_off = ((lane >> 4) << 3) + (lane & 7);
    const int b_col_off = ((lane >> 3) & 1) << 3;

    const unsigned w_sm_base = smem_u32(w_sm);

    unsigned ph = 0;

    // ---- prologue: stage-0 w via bulk copy, stage-0 s gathered directly ----
    if (tid == 0) {
        mbar_expect_tx(mbar, W_TILE_BYTES);
        bulk_copy(w_sm_base, (const char*)g_ws, W_TILE_BYTES, mbar);
    }
    {
        int pk01 = pspat[gp];
        int pk23 = pspat[64 + gp];
        int sp0 = pk01 & 0xFFFF, sp1 = ((unsigned)pk01) >> 16;
        int sp2 = pk23 & 0xFFFF, sp3 = ((unsigned)pk23) >> 16;
        float g0 = pwgt[gp], g1 = pwgt[64 + gp];
        float g2 = pwgt[128 + gp], g3 = pwgt[192 + gp];
        __nv_bfloat16 hv[4], lv[4];
#pragma unroll
        for (int j = 0; j < 4; ++j) {
            const float* pl = xbb + (((gc << 2) + j) << 12);
            float v = g0 * __ldg(pl + sp0) + g1 * __ldg(pl + sp1)
                    + g2 * __ldg(pl + sp2) + g3 * __ldg(pl + sp3);
            hv[j] = __float2bfloat16_rn(v);
            lv[j] = __float2bfloat16_rn(v - __bfloat162float(hv[j]));
        }
        *(uint2*)(s_sm + gp * WROW_ + (gc << 2)) =
            make_uint2(pkbf(hv[0], hv[1]), pkbf(hv[2], hv[3]));
        *(uint2*)(s_sm + S_SPL + gp * WROW_ + (gc << 2)) =
            make_uint2(pkbf(lv[0], lv[1]), pkbf(lv[2], lv[3]));
    }
    mbar_wait(mbar, ph); ph ^= 1;
    __syncthreads();

    // ---- 144 pipelined stages ----
    for (int s = 0; s < 144; ++s) {
        const __nv_bfloat16* sb = s_sm + (s & 1) * S_BUF;
        const __nv_bfloat16* wb = w_sm + (s & 1) * W_BUF;
        const int sn = s + 1;
        const int kk2 = sn >> 4;
        const int c0n = (sn & 15) << 4;

        // prefetch w(s+1): single bulk copy
        if (s < 143 && tid == 0) {
            mbar_expect_tx(mbar, W_TILE_BYTES);
            bulk_copy(w_sm_base + (unsigned)((sn & 1) * W_TILE_BYTES),
                      (const char*)g_ws + (size_t)sn * W_TILE_BYTES,
                      W_TILE_BYTES, mbar);
        }

        // next-stage gather state
        int sp0 = 0, sp1 = 0, sp2 = 0, sp3 = 0;
        float g0 = 0, g1 = 0, g2 = 0, g3 = 0;
        const float* pl_base = xbb;
        if (s < 143) {
            int pk01 = pspat[(kk2 << 7) + gp];
            int pk23 = pspat[(kk2 << 7) + 64 + gp];
            sp0 = pk01 & 0xFFFF; sp1 = ((unsigned)pk01) >> 16;
            sp2 = pk23 & 0xFFFF; sp3 = ((unsigned)pk23) >> 16;
            g0 = pwgt[(kk2 << 8) + gp];
            g1 = pwgt[(kk2 << 8) + 64 + gp];
            g2 = pwgt[(kk2 << 8) + 128 + gp];
            g3 = pwgt[(kk2 << 8) + 192 + gp];
            pl_base = xbb + ((c0n + (gc << 2)) << 12);
        }

        // A fragments (stage s)
        unsigned ah[2][4], al[2][4];
#pragma unroll
        for (int pt = 0; pt < 2; ++pt) {
            int prow = (pw << 5) + (pt << 4) + a_row_off;
            unsigned addr_h = smem_u32(sb + prow * WROW_ + a_col_off);
            unsigned addr_l = smem_u32(sb + S_SPL + prow * WROW_ + a_col_off);
            asm volatile("ldmatrix.sync.aligned.m8n8.x4.shared.b16 {%0,%1,%2,%3}, [%4];"
                : "=r"(ah[pt][0]), "=r"(ah[pt][1]), "=r"(ah[pt][2]), "=r"(ah[pt][3])
                : "r"(addr_h));
            asm volatile("ldmatrix.sync.aligned.m8n8.x4.shared.b16 {%0,%1,%2,%3}, [%4];"
                : "=r"(al[pt][0]), "=r"(al[pt][1]), "=r"(al[pt][2]), "=r"(al[pt][3])
                : "r"(addr_l));
        }

#define MMA(A, B0, B1, D) \
    asm volatile("mma.sync.aligned.m16n8k16.row.col.f32.bf16.bf16.f32 " \
        "{%0,%1,%2,%3},{%4,%5,%6,%7},{%8,%9},{%0,%1,%2,%3};" \
        : "+f"(D[0]), "+f"(D[1]), "+f"(D[2]), "+f"(D[3]) \
        : "r"(A[0]), "r"(A[1]), "r"(A[2]), "r"(A[3]), "r"(B0), "r"(B1))

#define MMA_OTP(otp_) do { \
    int orow = (ow << 6) + ((otp_) << 4) + b_row_off; \
    unsigned addr_h = smem_u32(wb + orow * WROW_ + b_col_off); \
    unsigned addr_l = smem_u32(wb + W_SPL + orow * WROW_ + b_col_off); \
    unsigned bh[4], bl[4]; \
    asm volatile("ldmatrix.sync.aligned.m8n8.x4.shared.b16 {%0,%1,%2,%3}, [%4];" \
        : "=r"(bh[0]), "=r"(bh[1]), "=r"(bh[2]), "=r"(bh[3]) : "r"(addr_h)); \
    asm volatile("ldmatrix.sync.aligned.m8n8.x4.shared.b16 {%0,%1,%2,%3}, [%4];" \
        : "=r"(bl[0]), "=r"(bl[1]), "=r"(bl[2]), "=r"(bl[3]) : "r"(addr_l)); \
    _Pragma("unroll") \
    for (int sub = 0; sub < 2; ++sub) { \
        int ot = ((otp_) << 1) + sub; \
        _Pragma("unroll") \
        for (int pt = 0; pt < 2; ++pt) { \
            float* d = acc[pt][ot]; \
            MMA(ah[pt], bh[sub * 2], bh[sub * 2 + 1], d); \
            MMA(al[pt], bh[sub * 2], bh[sub * 2 + 1], d); \
            MMA(ah[pt], bl[sub * 2], bl[sub * 2 + 1], d); \
        } \
    } \
} while (0)

        // ---- half 0: issue 8 gather loads (c j=0,1), mma otp 0-1, pack ----
        float la[8];
        if (s < 143) {
#pragma unroll
            for (int i = 0; i < 2; ++i) {
                const float* pl = pl_base + (i << 12);
                la[i * 4 + 0] = __ldg(pl + sp0);
                la[i * 4 + 1] = __ldg(pl + sp1);
                la[i * 4 + 2] = __ldg(pl + sp2);
                la[i * 4 + 3] = __ldg(pl + sp3);
            }
        }
        MMA_OTP(0);
        MMA_OTP(1);
        unsigned uh_x = 0, ul_x = 0;
        if (s < 143) {
            float v0 = g0 * la[0] + g1 * la[1] + g2 * la[2] + g3 * la[3];
            float v1 = g0 * la[4] + g1 * la[5] + g2 * la[6] + g3 * la[7];
            __nv_bfloat16 h0 = __float2bfloat16_rn(v0);
            __nv_bfloat16 h1 = __float2bfloat16_rn(v1);
            __nv_bfloat16 l0 = __float2bfloat16_rn(v0 - __bfloat162float(h0));
            __nv_bfloat16 l1 = __float2bfloat16_rn(v1 - __bfloat162float(h1));
            uh_x = pkbf(h0, h1);
            ul_x = pkbf(l0, l1);
        }

        // ---- half 1: issue 8 gather loads (c j=2,3), mma otp 2-3, store ----
        float lb[8];
        if (s < 143) {
#pragma unroll
            for (int i = 0; i < 2; ++i) {
                const float* pl = pl_base + ((i + 2) << 12);
                lb[i * 4 + 0] = __ldg(pl + sp0);
                lb[i * 4 + 1] = __ldg(pl + sp1);
                lb[i * 4 + 2] = __ldg(pl + sp2);
                lb[i * 4 + 3] = __ldg(pl + sp3);
            }
        }
        MMA_OTP(2);
        MMA_OTP(3);
        if (s < 143) {
            float v2 = g0 * lb[0] + g1 * lb[1] + g2 * lb[2] + g3 * lb[3];
            float v3 = g0 * lb[4] + g1 * lb[5] + g2 * lb[6] + g3 * lb[7];
            __nv_bfloat16 h2 = __float2bfloat16_rn(v2);
            __nv_bfloat16 h3 = __float2bfloat16_rn(v3);
            __nv_bfloat16 l2 = __float2bfloat16_rn(v2 - __bfloat162float(h2));
            __nv_bfloat16 l3 = __float2bfloat16_rn(v3 - __bfloat162float(h3));
            __nv_bfloat16* sbn = s_sm + (sn & 1) * S_BUF;
            *(uint2*)(sbn + gp * WROW_ + (gc << 2)) =
                make_uint2(uh_x, pkbf(h2, h3));
            *(uint2*)(sbn + S_SPL + gp * WROW_ + (gc << 2)) =
                make_uint2(ul_x, pkbf(l2, l3));
        }
#undef MMA_OTP
#undef MMA

        if (s < 143) { mbar_wait(mbar, ph); ph ^= 1; }
        __syncthreads();
    }

    // ---- epilogue: bias + fp32 stores ----
    const long ob_base = ((long)b << 8);
#pragma unroll
    for (int ot = 0; ot < 8; ++ot) {
        int oc = (ow << 6) + (ot << 3) + ((lane & 3) << 1);
        float b0 = __ldg(&bias[oc]);
        float b1 = __ldg(&bias[oc + 1]);
        float* o0p = out + ((ob_base + oc) << 12) + (y << 6);
        float* o1p = out + ((ob_base + oc + 1) << 12) + (y << 6);
#pragma unroll
        for (int pt = 0; pt < 2; ++pt) {
            const float* d = acc[pt][ot];
            int r0 = (pw << 5) + (pt << 4) + (lane >> 2);
            int r1 = r0 + 8;
            o0p[r0] = d[0] + b0;
            o1p[r0] = d[1] + b1;
            o0p[r1] = d[2] + b0;
            o1p[r1] = d[3] + b1;
        }
    }
}

// ---------------------------------------------------------------------------
// Launch: inputs per metadata order: input, coord_offset, coord_weight, weight, bias
// ---------------------------------------------------------------------------
extern "C" void kernel_launch(void* const* d_in, const int* in_sizes, int n_in,
                              void* d_out, int out_size) {
    const float* x    = (const float*)d_in[0];
    const float* coff = (const float*)d_in[1];
    const float* cwt  = (const float*)d_in[2];
    const float* wt   = (const float*)d_in[3];
    const float* bias = (const float*)d_in[4];
    float* out = (float*)d_out;

    static int smem_set = 0;
    if (!smem_set) {
        cudaFuncSetAttribute(dcn_main,
                             cudaFuncAttributeMaxDynamicSharedMemorySize,
                             SM_TOT);
        smem_set = 1;
    }

    int n_ws = KK_ * 16 * 2 * O_ * WROW_;
    dcn_split_w<<<(n_ws + 255) / 256, 256>>>(wt);
    dcn_main<<<B_ * H_, 256, SM_TOT>>>(x, coff, cwt, bias, out);
}